// round 14
// baseline (speedup 1.0000x reference)
#include <cuda_runtime.h>
#include <cuda_bf16.h>
#include <cstdint>
#include <cstddef>

#define B_ 1024
#define E_ 8192
#define R_ 16
#define D_ 128
#define BT 64            // b per tile (A rows: 64 h + 64 t = 128, 8-row interleaved)
#define ET2 128          // e per tile (N)
#define NTILE_E (E_/ET2) // 64
#define TILES_PER_CTA 2
#define NEG (NTILE_E/TILES_PER_CTA)   // 32 e-groups
#define NCONV 512
#define NBATCH (B_/8)

// ---- global scratch (no allocation allowed) ----
__device__ float g_c[R_*E_];       // c[r,e] = zz[e] - 2*rz[r,e]
__device__ float g_zz[E_];
__device__ float g_g[E_];          // g[e]   = zz[e] + 2*zq[e]
__device__ float g_u[B_*R_];       // u[b,r]
__device__ float g_v[B_];          // v[b]
__device__ float g_part[B_*NEG];   // [b][e-group]
__device__ __nv_bfloat16 g_Ebf[E_*D_];
__device__ __nv_bfloat16 g_Rbf[R_*D_];

__device__ __forceinline__ float wsum(float v){
  v += __shfl_xor_sync(0xffffffffu, v, 16);
  v += __shfl_xor_sync(0xffffffffu, v, 8);
  v += __shfl_xor_sync(0xffffffffu, v, 4);
  v += __shfl_xor_sync(0xffffffffu, v, 2);
  v += __shfl_xor_sync(0xffffffffu, v, 1);
  return v;
}
__device__ __forceinline__ float hsum16(float v){
  v += __shfl_xor_sync(0xffffffffu, v, 1);
  v += __shfl_xor_sync(0xffffffffu, v, 2);
  v += __shfl_xor_sync(0xffffffffu, v, 4);
  v += __shfl_xor_sync(0xffffffffu, v, 8);
  return v;
}
__device__ __forceinline__ float dot4(float4 a, float4 b){
  return fmaf(a.x,b.x, fmaf(a.y,b.y, fmaf(a.z,b.z, a.w*b.w)));
}
__device__ __forceinline__ float sqrt_approx(float x){
  float y; asm("sqrt.approx.f32 %0, %1;" : "=f"(y) : "f"(x)); return y;
}
__device__ __forceinline__ uint32_t smem_u32(const void* p){
  uint32_t a;
  asm("{ .reg .u64 t; cvta.to.shared.u64 t, %1; cvt.u32.u64 %0, t; }" : "=r"(a) : "l"(p));
  return a;
}
__device__ __forceinline__ void ldm4(uint32_t& r0, uint32_t& r1, uint32_t& r2, uint32_t& r3,
                                     uint32_t addr){
  asm volatile("ldmatrix.sync.aligned.m8n8.x4.shared.b16 {%0,%1,%2,%3}, [%4];"
    : "=r"(r0), "=r"(r1), "=r"(r2), "=r"(r3) : "r"(addr));
}
__device__ __forceinline__ void mma16816(float* d, const uint32_t* a, uint32_t b0, uint32_t b1){
  asm volatile("mma.sync.aligned.m16n8k16.row.col.f32.bf16.bf16.f32 "
    "{%0,%1,%2,%3}, {%4,%5,%6,%7}, {%8,%9}, {%0,%1,%2,%3};"
    : "+f"(d[0]), "+f"(d[1]), "+f"(d[2]), "+f"(d[3])
    : "r"(a[0]), "r"(a[1]), "r"(a[2]), "r"(a[3]), "r"(b0), "r"(b1));
}
#define CP_ASYNC16(smaddr, gptr) \
  asm volatile("cp.async.cg.shared.global [%0], [%1], 16;" :: "r"(smaddr), "l"(gptr) : "memory")
#define CP_COMMIT() asm volatile("cp.async.commit_group;" ::: "memory")
#define CP_WAIT0()  asm volatile("cp.async.wait_group 0;" ::: "memory")

// ---------------- k_pre: convert(+zz,g) | batch dots | rules convert ----------------
__global__ void k_pre(const float* __restrict__ Etab,
                      const float* __restrict__ rules,
                      const int* __restrict__ head,
                      const int* __restrict__ tail,
                      const int* __restrict__ qrelp){
  int tid = threadIdx.x, bx = blockIdx.x;

  if (bx < NCONV){
    int qrel = __ldg(qrelp);
    int idx = bx*256 + tid;
    const float4* s = (const float4*)Etab;
    float4 a = __ldg(s + idx*2), b = __ldg(s + idx*2 + 1);
    unsigned short hs[8];
    hs[0]=__bfloat16_as_ushort(__float2bfloat16(a.x));
    hs[1]=__bfloat16_as_ushort(__float2bfloat16(a.y));
    hs[2]=__bfloat16_as_ushort(__float2bfloat16(a.z));
    hs[3]=__bfloat16_as_ushort(__float2bfloat16(a.w));
    hs[4]=__bfloat16_as_ushort(__float2bfloat16(b.x));
    hs[5]=__bfloat16_as_ushort(__float2bfloat16(b.y));
    hs[6]=__bfloat16_as_ushort(__float2bfloat16(b.z));
    hs[7]=__bfloat16_as_ushort(__float2bfloat16(b.w));
    uint4 u;
    u.x = (uint32_t)hs[0] | ((uint32_t)hs[1]<<16);
    u.y = (uint32_t)hs[2] | ((uint32_t)hs[3]<<16);
    u.z = (uint32_t)hs[4] | ((uint32_t)hs[5]<<16);
    u.w = (uint32_t)hs[6] | ((uint32_t)hs[7]<<16);
    ((uint4*)g_Ebf)[idx] = u;
    const float4* q4 = (const float4*)(rules + (size_t)qrel*D_) + (idx & 15)*2;
    float4 qa = __ldg(q4), qb = __ldg(q4 + 1);
    float zz8 = dot4(a,a) + dot4(b,b);
    float zq8 = dot4(a,qa) + dot4(b,qb);
    zz8 = hsum16(zz8);
    zq8 = hsum16(zq8);
    if ((tid & 15) == 0){
      int e = idx >> 4;
      g_zz[e] = zz8;
      g_g[e]  = zz8 + 2.f*zq8;
    }
    return;
  }

  if (bx == NCONV + NBATCH){
    const float4* s = (const float4*)rules;
    float4 a = __ldg(s + tid*2), b = __ldg(s + tid*2 + 1);
    unsigned short hs[8];
    hs[0]=__bfloat16_as_ushort(__float2bfloat16(a.x));
    hs[1]=__bfloat16_as_ushort(__float2bfloat16(a.y));
    hs[2]=__bfloat16_as_ushort(__float2bfloat16(a.z));
    hs[3]=__bfloat16_as_ushort(__float2bfloat16(a.w));
    hs[4]=__bfloat16_as_ushort(__float2bfloat16(b.x));
    hs[5]=__bfloat16_as_ushort(__float2bfloat16(b.y));
    hs[6]=__bfloat16_as_ushort(__float2bfloat16(b.z));
    hs[7]=__bfloat16_as_ushort(__float2bfloat16(b.w));
    uint4 u;
    u.x = (uint32_t)hs[0] | ((uint32_t)hs[1]<<16);
    u.y = (uint32_t)hs[2] | ((uint32_t)hs[3]<<16);
    u.z = (uint32_t)hs[4] | ((uint32_t)hs[5]<<16);
    u.w = (uint32_t)hs[6] | ((uint32_t)hs[7]<<16);
    ((uint4*)g_Rbf)[tid] = u;
    return;
  }

  __shared__ __align__(16) float rs[R_*D_];
  __shared__ float rr[R_];
  for (int i = tid; i < R_*D_; i += 256) rs[i] = rules[i];
  __syncthreads();
  if (tid < R_){
    float s = 0.f;
    for (int k = 0; k < D_; k++) s = fmaf(rs[tid*D_+k], rs[tid*D_+k], s);
    rr[tid] = s;
  }
  __syncthreads();
  int qrel = *qrelp;
  int lane = tid & 31, warp = tid >> 5;
  int b = (bx - NCONV)*8 + warp;
  float4 hv = ((const float4*)(Etab + (size_t)head[b]*D_))[lane];
  float4 tv = ((const float4*)(Etab + (size_t)tail[b]*D_))[lane];
  float hh = wsum(dot4(hv, hv));
  float tt = wsum(dot4(tv, tv));
  float4 qv = ((const float4*)(rs + qrel*D_))[lane];
  float tq = wsum(dot4(tv, qv));
  if (lane == 0) g_v[b] = tt + rr[qrel] - 2.f*tq;
  #pragma unroll
  for (int r = 0; r < R_; r++){
    float4 rv = ((const float4*)(rs + r*D_))[lane];
    float hr = wsum(dot4(hv, rv));
    if (lane == 0) g_u[b*R_ + r] = hh + rr[r] + 2.f*hr;
  }
}

// ---------------- k_rz: c[r,e] = zz[e] - 2*(rules . z) via bf16 mma ----------------
#define RZ_OFF_B 4096
#define RZ_OFF_ZZ 69632
#define RZ_SMEM 70656

__global__ __launch_bounds__(256) void k_rz(){
  extern __shared__ __align__(16) char smc[];
  uint32_t sb = smem_u32(smc);
  float* zsm = (float*)(smc + RZ_OFF_ZZ);
  int tid = threadIdx.x, wid = tid >> 5, lane = tid & 31;
  int e0 = blockIdx.x * 256;

  {
    const uint4* Rb = (const uint4*)g_Rbf;
    int ch = tid & 15, row = tid >> 4;
    uint4 v = Rb[row*16 + ch];
    *(uint4*)(smc + row*256 + (((uint32_t)ch ^ (row & 7)) << 4)) = v;
  }
  const uint4* T = (const uint4*)g_Ebf;
  #pragma unroll
  for (int it = 0; it < 16; it++){
    int idx = it*256 + tid;
    int ch = idx & 15, row = idx >> 4;
    uint4 v = T[(size_t)(e0 + row)*16 + ch];
    *(uint4*)(smc + RZ_OFF_B + row*256 + (((uint32_t)ch ^ (row & 7)) << 4)) = v;
  }
  zsm[tid] = g_zz[e0 + tid];
  __syncthreads();

  int lrow = lane & 15, lhi = lane >> 4;
  uint32_t a_base = sb + lrow*256;
  uint32_t a_sw = (uint32_t)(lrow & 7);
  uint32_t b_base[2], b_sw[2];
  #pragma unroll
  for (int nj = 0; nj < 2; nj++){
    int r = wid*32 + nj*16 + lrow;
    b_base[nj] = sb + RZ_OFF_B + r*256; b_sw[nj] = (uint32_t)(r & 7);
  }

  float acc[4][4];
  #pragma unroll
  for (int ni = 0; ni < 4; ni++)
    #pragma unroll
    for (int q = 0; q < 4; q++) acc[ni][q] = 0.f;

  #pragma unroll
  for (int kk = 0; kk < 8; kk++){
    uint32_t c = (uint32_t)(kk*2 + lhi);
    uint32_t ra[4], rb[2][4];
    ldm4(ra[0], ra[1], ra[2], ra[3], a_base + ((c ^ a_sw) << 4));
    #pragma unroll
    for (int nj = 0; nj < 2; nj++)
      ldm4(rb[nj][0], rb[nj][1], rb[nj][2], rb[nj][3],
           b_base[nj] + ((c ^ b_sw[nj]) << 4));
    #pragma unroll
    for (int ni = 0; ni < 4; ni++){
      int nj = ni >> 1, sub = ni & 1;
      mma16816(acc[ni], ra, rb[nj][sub], rb[nj][2+sub]);
    }
  }

  int r0 = lane >> 2, ecol = (lane & 3)*2;
  #pragma unroll
  for (int ni = 0; ni < 4; ni++){
    int el = wid*32 + ni*8 + ecol;
    float z0 = zsm[el], z1 = zsm[el+1];
    int eg = e0 + el;
    *(float2*)(g_c + (size_t)r0*E_ + eg)
      = make_float2(fmaf(-2.f, acc[ni][0], z0), fmaf(-2.f, acc[ni][1], z1));
    *(float2*)(g_c + (size_t)(r0+8)*E_ + eg)
      = make_float2(fmaf(-2.f, acc[ni][2], z0), fmaf(-2.f, acc[ni][3], z1));
  }
}

// ---------------- main persistent multi-tile mma.sync kernel ----------------
// SMEM: A @0 (32KB) | B0 @32768 | B1 @65536 | us @98304 (4KB) | vs @102400
//       hix @102656 | tix @102912 | red @103168 (1KB)  -> 104192 bytes
#define OFF_B0  32768
#define OFF_B1  65536
#define OFF_US  98304
#define OFF_VS  102400
#define OFF_HIX 102656
#define OFF_TIX 102912
#define OFF_RED 103168
#define SMEM_BYTES 104192

__global__ __launch_bounds__(256,2) void k_main(const int* __restrict__ head,
                                                const int* __restrict__ tail){
  extern __shared__ __align__(16) char smc[];
  uint32_t sb = smem_u32(smc);
  float* us = (float*)(smc + OFF_US);    // [64][16]
  float* vs = (float*)(smc + OFF_VS);    // [64]
  int* hix = (int*)(smc + OFF_HIX);
  int* tix = (int*)(smc + OFF_TIX);
  float* red = (float*)(smc + OFF_RED);  // [4][64]

  int tid = threadIdx.x, wid = tid >> 5, lane = tid & 31;
  int b0 = blockIdx.y * BT;
  int et0 = blockIdx.x * TILES_PER_CTA;  // first e-tile index

  if (tid < 64){ hix[tid] = head[b0+tid]; tix[tid] = tail[b0+tid]; vs[tid] = g_v[b0+tid]; }
  for (int i = tid; i < BT*R_; i += 256) us[i] = g_u[b0*R_ + i];

  // ---- A tile (h/t interleaved in 8-row blocks), regular LDG->STS ----
  const uint4* T = (const uint4*)g_Ebf;
  #pragma unroll
  for (int it = 0; it < 8; it++){
    int idx = it*256 + tid;
    int ch = idx & 15, row = idx >> 4;   // row 0..127
    int bl = ((row >> 4) << 3) | (row & 7);
    int ent = (row & 8) ? tix[bl] : hix[bl];
    uint4 v = T[(size_t)ent*16 + ch];
    *(uint4*)(smc + row*256 + (((uint32_t)ch ^ (row & 7)) << 4)) = v;
  }

  // ---- prefetch B tile 0 via cp.async ----
  {
    int e0t = (et0)*ET2;
    #pragma unroll
    for (int it = 0; it < 8; it++){
      int idx = it*256 + tid;
      int ch = idx & 15, row = idx >> 4;
      uint32_t dst = sb + OFF_B0 + row*256 + (((uint32_t)ch ^ (row & 7)) << 4);
      CP_ASYNC16(dst, (const uint4*)g_Ebf + (size_t)(e0t + row)*16 + ch);
    }
    CP_COMMIT();
  }

  // per-thread fragment coordinates
  int wm = wid >> 2, wn = wid & 3;
  int lrow = lane & 15, lhi = lane >> 4;
  uint32_t a_base[4], a_sw[4];
  #pragma unroll
  for (int mi = 0; mi < 4; mi++){
    int r = wm*64 + mi*16 + lrow;
    a_base[mi] = sb + r*256; a_sw[mi] = (uint32_t)(r & 7);
  }
  int brow = lane >> 2, ecol = (lane & 3)*2;
  int eb = wn*32 + ecol;

  float bacc[4];   // per-mi partials accumulated across tiles (valid at lane&3==0)
  #pragma unroll
  for (int mi = 0; mi < 4; mi++) bacc[mi] = 0.f;

  for (int t = 0; t < TILES_PER_CTA; t++){
    CP_WAIT0();
    __syncthreads();

    // prefetch next B tile into the other buffer
    if (t < TILES_PER_CTA-1){
      int e0n = (et0 + t + 1)*ET2;
      uint32_t boff = ((t+1) & 1) ? OFF_B1 : OFF_B0;
      #pragma unroll
      for (int it = 0; it < 8; it++){
        int idx = it*256 + tid;
        int ch = idx & 15, row = idx >> 4;
        uint32_t dst = sb + boff + row*256 + (((uint32_t)ch ^ (row & 7)) << 4);
        CP_ASYNC16(dst, (const uint4*)g_Ebf + (size_t)(e0n + row)*16 + ch);
      }
      CP_COMMIT();
    }

    uint32_t bbuf = sb + ((t & 1) ? OFF_B1 : OFF_B0);
    uint32_t b_base[2], b_sw[2];
    #pragma unroll
    for (int nj = 0; nj < 2; nj++){
      int r = wn*32 + nj*16 + lrow;
      b_base[nj] = bbuf + r*256; b_sw[nj] = (uint32_t)(r & 7);
    }

    float acc[4][4][4];
    #pragma unroll
    for (int mi = 0; mi < 4; mi++)
      #pragma unroll
      for (int ni = 0; ni < 4; ni++)
        #pragma unroll
        for (int q = 0; q < 4; q++) acc[mi][ni][q] = 0.f;

    #pragma unroll
    for (int kk = 0; kk < 8; kk++){
      uint32_t c = (uint32_t)(kk*2 + lhi);
      uint32_t ra[4][4], rb[2][4];
      #pragma unroll
      for (int mi = 0; mi < 4; mi++)
        ldm4(ra[mi][0], ra[mi][1], ra[mi][2], ra[mi][3],
             a_base[mi] + ((c ^ a_sw[mi]) << 4));
      #pragma unroll
      for (int nj = 0; nj < 2; nj++)
        ldm4(rb[nj][0], rb[nj][1], rb[nj][2], rb[nj][3],
             b_base[nj] + ((c ^ b_sw[nj]) << 4));
      #pragma unroll
      for (int mi = 0; mi < 4; mi++)
        #pragma unroll
        for (int ni = 0; ni < 4; ni++){
          int nj = ni >> 1, sub = ni & 1;
          mma16816(acc[mi][ni], ra[mi], rb[nj][sub], rb[nj][2+sub]);
        }
    }

    // ---- in-register epilogue; c/g read from L2-hot gmem ----
    int e0t = (et0 + t)*ET2;
    const float* cg = g_c + e0t + eb;
    const float* gg_p = g_g + e0t + eb;

    #pragma unroll
    for (int ni = 0; ni < 4; ni++){
      float2 gg = __ldg((const float2*)(gg_p + ni*8));
      #pragma unroll
      for (int mi = 0; mi < 4; mi++){
        int bl = (wm*4 + mi)*8 + brow;
        float vb = vs[bl];
        acc[mi][ni][2] = sqrt_approx(fmaxf(fmaf(-2.f, acc[mi][ni][2], vb + gg.x), 0.f));
        acc[mi][ni][3] = sqrt_approx(fmaxf(fmaf(-2.f, acc[mi][ni][3], vb + gg.y), 0.f));
      }
    }

    float S1[4][4][2];
    #pragma unroll
    for (int mi = 0; mi < 4; mi++)
      #pragma unroll
      for (int ni = 0; ni < 4; ni++){ S1[mi][ni][0] = 0.f; S1[mi][ni][1] = 0.f; }

    #pragma unroll
    for (int r = 0; r < R_; r++){
      float2 cr[4];
      #pragma unroll
      for (int ni = 0; ni < 4; ni++)
        cr[ni] = __ldg((const float2*)(cg + (size_t)r*E_ + ni*8));
      #pragma unroll
      for (int mi = 0; mi < 4; mi++){
        int bl = (wm*4 + mi)*8 + brow;
        float ur = us[bl*R_ + r];
        #pragma unroll
        for (int ni = 0; ni < 4; ni++){
          S1[mi][ni][0] += sqrt_approx(fmaxf(fmaf(-2.f, acc[mi][ni][0], ur + cr[ni].x), 0.f));
          S1[mi][ni][1] += sqrt_approx(fmaxf(fmaf(-2.f, acc[mi][ni][1], ur + cr[ni].y), 0.f));
        }
      }
    }

    #pragma unroll
    for (int mi = 0; mi < 4; mi++){
      float s = 0.f;
      #pragma unroll
      for (int ni = 0; ni < 4; ni++)
        s = fmaf(S1[mi][ni][0], acc[mi][ni][2], fmaf(S1[mi][ni][1], acc[mi][ni][3], s));
      s += __shfl_xor_sync(0xffffffffu, s, 1);
      s += __shfl_xor_sync(0xffffffffu, s, 2);
      bacc[mi] += s;
    }
  }

  // ---- single cross-warp reduction at the end ----
  #pragma unroll
  for (int mi = 0; mi < 4; mi++){
    if ((lane & 3) == 0){
      int bl = (wm*4 + mi)*8 + brow;
      red[wn*64 + bl] = bacc[mi];
    }
  }
  __syncthreads();
  if (tid < 64){
    float s = (red[tid] + red[64+tid]) + (red[128+tid] + red[192+tid]);
    g_part[(size_t)(b0 + tid)*NEG + blockIdx.x] = s;
  }
}

// ---------------- final deterministic reduction (32 partials per b) ----------------
__global__ void k_final(float* __restrict__ out){
  int wid = threadIdx.x >> 5, lane = threadIdx.x & 31;
  int b = blockIdx.x*8 + wid;
  float s = g_part[(size_t)b*NEG + lane];
  s = wsum(s);
  if (lane == 0) out[b] = s * (1.f/(float)E_);
}

extern "C" void kernel_launch(void* const* d_in, const int* in_sizes, int n_in,
                              void* d_out, int out_size){
  const int*   head  = (const int*)d_in[0];
  const int*   tail  = (const int*)d_in[1];
  const int*   qrel  = (const int*)d_in[2];
  // d_in[3] = depth (fixed at 1, unused)
  const float* Etab  = (const float*)d_in[4];
  const float* rules = (const float*)d_in[5];
  float* out = (float*)d_out;

  cudaFuncSetAttribute(k_main, cudaFuncAttributeMaxDynamicSharedMemorySize, SMEM_BYTES);
  cudaFuncSetAttribute(k_rz, cudaFuncAttributeMaxDynamicSharedMemorySize, RZ_SMEM);

  k_pre<<<NCONV + NBATCH + 1, 256>>>(Etab, rules, head, tail, qrel);
  k_rz<<<E_/256, 256, RZ_SMEM>>>();
  dim3 grid(NEG, B_/BT);
  k_main<<<grid, 256, SMEM_BYTES>>>(head, tail);
  k_final<<<B_/8, 256>>>(out);
}

// round 16
// speedup vs baseline: 1.1418x; 1.1418x over previous
#include <cuda_runtime.h>
#include <cuda_bf16.h>
#include <cstdint>
#include <cstddef>

#define B_ 1024
#define E_ 8192
#define R_ 16
#define D_ 128
#define BT 64            // b per tile (A rows: 64 h + 64 t = 128, 8-row interleaved)
#define ETW 64           // e-tile width (N)
#define TILES_PER_CTA 2
#define NEG (E_/(ETW*TILES_PER_CTA))  // 64 e-groups
#define NCONV 512
#define NBATCH (B_/8)

// ---- global scratch (no allocation allowed) ----
__device__ float g_c[R_*E_];       // c[r,e] = zz[e] - 2*rz[r,e]
__device__ float g_zz[E_];
__device__ float g_g[E_];          // g[e]   = zz[e] + 2*zq[e]
__device__ float g_u[B_*R_];       // u[b,r]
__device__ float g_v[B_];          // v[b]
__device__ float g_part[B_*NEG];   // [b][e-group]
__device__ __nv_bfloat16 g_Ebf[E_*D_];
__device__ __nv_bfloat16 g_Rbf[R_*D_];

__device__ __forceinline__ float wsum(float v){
  v += __shfl_xor_sync(0xffffffffu, v, 16);
  v += __shfl_xor_sync(0xffffffffu, v, 8);
  v += __shfl_xor_sync(0xffffffffu, v, 4);
  v += __shfl_xor_sync(0xffffffffu, v, 2);
  v += __shfl_xor_sync(0xffffffffu, v, 1);
  return v;
}
__device__ __forceinline__ float hsum16(float v){
  v += __shfl_xor_sync(0xffffffffu, v, 1);
  v += __shfl_xor_sync(0xffffffffu, v, 2);
  v += __shfl_xor_sync(0xffffffffu, v, 4);
  v += __shfl_xor_sync(0xffffffffu, v, 8);
  return v;
}
__device__ __forceinline__ float dot4(float4 a, float4 b){
  return fmaf(a.x,b.x, fmaf(a.y,b.y, fmaf(a.z,b.z, a.w*b.w)));
}
__device__ __forceinline__ float sqrt_approx(float x){
  float y; asm("sqrt.approx.f32 %0, %1;" : "=f"(y) : "f"(x)); return y;
}
__device__ __forceinline__ uint32_t smem_u32(const void* p){
  uint32_t a;
  asm("{ .reg .u64 t; cvta.to.shared.u64 t, %1; cvt.u32.u64 %0, t; }" : "=r"(a) : "l"(p));
  return a;
}
__device__ __forceinline__ void ldm4(uint32_t& r0, uint32_t& r1, uint32_t& r2, uint32_t& r3,
                                     uint32_t addr){
  asm volatile("ldmatrix.sync.aligned.m8n8.x4.shared.b16 {%0,%1,%2,%3}, [%4];"
    : "=r"(r0), "=r"(r1), "=r"(r2), "=r"(r3) : "r"(addr));
}
__device__ __forceinline__ void mma16816(float* d, const uint32_t* a, uint32_t b0, uint32_t b1){
  asm volatile("mma.sync.aligned.m16n8k16.row.col.f32.bf16.bf16.f32 "
    "{%0,%1,%2,%3}, {%4,%5,%6,%7}, {%8,%9}, {%0,%1,%2,%3};"
    : "+f"(d[0]), "+f"(d[1]), "+f"(d[2]), "+f"(d[3])
    : "r"(a[0]), "r"(a[1]), "r"(a[2]), "r"(a[3]), "r"(b0), "r"(b1));
}
#define CP_ASYNC16(smaddr, gptr) \
  asm volatile("cp.async.cg.shared.global [%0], [%1], 16;" :: "r"(smaddr), "l"(gptr) : "memory")
#define CP_COMMIT() asm volatile("cp.async.commit_group;" ::: "memory")
#define CP_WAIT0()  asm volatile("cp.async.wait_group 0;" ::: "memory")

// ---------------- k_pre: convert(+zz,g) | batch dots | rules convert ----------------
__global__ void k_pre(const float* __restrict__ Etab,
                      const float* __restrict__ rules,
                      const int* __restrict__ head,
                      const int* __restrict__ tail,
                      const int* __restrict__ qrelp){
  int tid = threadIdx.x, bx = blockIdx.x;

  if (bx < NCONV){
    int qrel = __ldg(qrelp);
    int idx = bx*256 + tid;
    const float4* s = (const float4*)Etab;
    float4 a = __ldg(s + idx*2), b = __ldg(s + idx*2 + 1);
    unsigned short hs[8];
    hs[0]=__bfloat16_as_ushort(__float2bfloat16(a.x));
    hs[1]=__bfloat16_as_ushort(__float2bfloat16(a.y));
    hs[2]=__bfloat16_as_ushort(__float2bfloat16(a.z));
    hs[3]=__bfloat16_as_ushort(__float2bfloat16(a.w));
    hs[4]=__bfloat16_as_ushort(__float2bfloat16(b.x));
    hs[5]=__bfloat16_as_ushort(__float2bfloat16(b.y));
    hs[6]=__bfloat16_as_ushort(__float2bfloat16(b.z));
    hs[7]=__bfloat16_as_ushort(__float2bfloat16(b.w));
    uint4 u;
    u.x = (uint32_t)hs[0] | ((uint32_t)hs[1]<<16);
    u.y = (uint32_t)hs[2] | ((uint32_t)hs[3]<<16);
    u.z = (uint32_t)hs[4] | ((uint32_t)hs[5]<<16);
    u.w = (uint32_t)hs[6] | ((uint32_t)hs[7]<<16);
    ((uint4*)g_Ebf)[idx] = u;
    const float4* q4 = (const float4*)(rules + (size_t)qrel*D_) + (idx & 15)*2;
    float4 qa = __ldg(q4), qb = __ldg(q4 + 1);
    float zz8 = dot4(a,a) + dot4(b,b);
    float zq8 = dot4(a,qa) + dot4(b,qb);
    zz8 = hsum16(zz8);
    zq8 = hsum16(zq8);
    if ((tid & 15) == 0){
      int e = idx >> 4;
      g_zz[e] = zz8;
      g_g[e]  = zz8 + 2.f*zq8;
    }
    return;
  }

  if (bx == NCONV + NBATCH){
    const float4* s = (const float4*)rules;
    float4 a = __ldg(s + tid*2), b = __ldg(s + tid*2 + 1);
    unsigned short hs[8];
    hs[0]=__bfloat16_as_ushort(__float2bfloat16(a.x));
    hs[1]=__bfloat16_as_ushort(__float2bfloat16(a.y));
    hs[2]=__bfloat16_as_ushort(__float2bfloat16(a.z));
    hs[3]=__bfloat16_as_ushort(__float2bfloat16(a.w));
    hs[4]=__bfloat16_as_ushort(__float2bfloat16(b.x));
    hs[5]=__bfloat16_as_ushort(__float2bfloat16(b.y));
    hs[6]=__bfloat16_as_ushort(__float2bfloat16(b.z));
    hs[7]=__bfloat16_as_ushort(__float2bfloat16(b.w));
    uint4 u;
    u.x = (uint32_t)hs[0] | ((uint32_t)hs[1]<<16);
    u.y = (uint32_t)hs[2] | ((uint32_t)hs[3]<<16);
    u.z = (uint32_t)hs[4] | ((uint32_t)hs[5]<<16);
    u.w = (uint32_t)hs[6] | ((uint32_t)hs[7]<<16);
    ((uint4*)g_Rbf)[tid] = u;
    return;
  }

  __shared__ __align__(16) float rs[R_*D_];
  __shared__ float rr[R_];
  for (int i = tid; i < R_*D_; i += 256) rs[i] = rules[i];
  __syncthreads();
  if (tid < R_){
    float s = 0.f;
    for (int k = 0; k < D_; k++) s = fmaf(rs[tid*D_+k], rs[tid*D_+k], s);
    rr[tid] = s;
  }
  __syncthreads();
  int qrel = *qrelp;
  int lane = tid & 31, warp = tid >> 5;
  int b = (bx - NCONV)*8 + warp;
  float4 hv = ((const float4*)(Etab + (size_t)head[b]*D_))[lane];
  float4 tv = ((const float4*)(Etab + (size_t)tail[b]*D_))[lane];
  float hh = wsum(dot4(hv, hv));
  float tt = wsum(dot4(tv, tv));
  float4 qv = ((const float4*)(rs + qrel*D_))[lane];
  float tq = wsum(dot4(tv, qv));
  if (lane == 0) g_v[b] = tt + rr[qrel] - 2.f*tq;
  #pragma unroll
  for (int r = 0; r < R_; r++){
    float4 rv = ((const float4*)(rs + r*D_))[lane];
    float hr = wsum(dot4(hv, rv));
    if (lane == 0) g_u[b*R_ + r] = hh + rr[r] + 2.f*hr;
  }
}

// ---------------- k_rz: c[r,e] = zz[e] - 2*(rules . z) via bf16 mma ----------------
#define RZ_OFF_B 4096
#define RZ_OFF_ZZ 69632
#define RZ_SMEM 70656

__global__ __launch_bounds__(256) void k_rz(){
  extern __shared__ __align__(16) char smc[];
  uint32_t sb = smem_u32(smc);
  float* zsm = (float*)(smc + RZ_OFF_ZZ);
  int tid = threadIdx.x, wid = tid >> 5, lane = tid & 31;
  int e0 = blockIdx.x * 256;

  {
    const uint4* Rb = (const uint4*)g_Rbf;
    int ch = tid & 15, row = tid >> 4;
    uint4 v = Rb[row*16 + ch];
    *(uint4*)(smc + row*256 + (((uint32_t)ch ^ (row & 7)) << 4)) = v;
  }
  const uint4* T = (const uint4*)g_Ebf;
  #pragma unroll
  for (int it = 0; it < 16; it++){
    int idx = it*256 + tid;
    int ch = idx & 15, row = idx >> 4;
    uint4 v = T[(size_t)(e0 + row)*16 + ch];
    *(uint4*)(smc + RZ_OFF_B + row*256 + (((uint32_t)ch ^ (row & 7)) << 4)) = v;
  }
  zsm[tid] = g_zz[e0 + tid];
  __syncthreads();

  int lrow = lane & 15, lhi = lane >> 4;
  uint32_t a_base = sb + lrow*256;
  uint32_t a_sw = (uint32_t)(lrow & 7);
  uint32_t b_base[2], b_sw[2];
  #pragma unroll
  for (int nj = 0; nj < 2; nj++){
    int r = wid*32 + nj*16 + lrow;
    b_base[nj] = sb + RZ_OFF_B + r*256; b_sw[nj] = (uint32_t)(r & 7);
  }

  float acc[4][4];
  #pragma unroll
  for (int ni = 0; ni < 4; ni++)
    #pragma unroll
    for (int q = 0; q < 4; q++) acc[ni][q] = 0.f;

  #pragma unroll
  for (int kk = 0; kk < 8; kk++){
    uint32_t c = (uint32_t)(kk*2 + lhi);
    uint32_t ra[4], rb[2][4];
    ldm4(ra[0], ra[1], ra[2], ra[3], a_base + ((c ^ a_sw) << 4));
    #pragma unroll
    for (int nj = 0; nj < 2; nj++)
      ldm4(rb[nj][0], rb[nj][1], rb[nj][2], rb[nj][3],
           b_base[nj] + ((c ^ b_sw[nj]) << 4));
    #pragma unroll
    for (int ni = 0; ni < 4; ni++){
      int nj = ni >> 1, sub = ni & 1;
      mma16816(acc[ni], ra, rb[nj][sub], rb[nj][2+sub]);
    }
  }

  int r0 = lane >> 2, ecol = (lane & 3)*2;
  #pragma unroll
  for (int ni = 0; ni < 4; ni++){
    int el = wid*32 + ni*8 + ecol;
    float z0 = zsm[el], z1 = zsm[el+1];
    int eg = e0 + el;
    *(float2*)(g_c + (size_t)r0*E_ + eg)
      = make_float2(fmaf(-2.f, acc[ni][0], z0), fmaf(-2.f, acc[ni][1], z1));
    *(float2*)(g_c + (size_t)(r0+8)*E_ + eg)
      = make_float2(fmaf(-2.f, acc[ni][2], z0), fmaf(-2.f, acc[ni][3], z1));
  }
}

// ---------------- main mma.sync kernel: 128x64 tiles, occ 3 ----------------
// SMEM: A @0 (32KB) | B0 @32768 (16KB) | B1 @49152 (16KB) | us @65536 (4KB)
//       vs @69632 | hix @69888 | tix @70144 | red @70400 (1KB) -> 71424
#define OFF_B0  32768
#define OFF_B1  49152
#define OFF_US  65536
#define OFF_VS  69632
#define OFF_HIX 69888
#define OFF_TIX 70144
#define OFF_RED 70400
#define SMEM_BYTES 71424

__global__ __launch_bounds__(256,3) void k_main(const int* __restrict__ head,
                                                const int* __restrict__ tail){
  extern __shared__ __align__(16) char smc[];
  uint32_t sb = smem_u32(smc);
  float* us = (float*)(smc + OFF_US);    // [64][16]
  float* vs = (float*)(smc + OFF_VS);    // [64]
  int* hix = (int*)(smc + OFF_HIX);
  int* tix = (int*)(smc + OFF_TIX);
  float* red = (float*)(smc + OFF_RED);  // [4][64]

  int tid = threadIdx.x, wid = tid >> 5, lane = tid & 31;
  int b0 = blockIdx.y * BT;
  int e00 = blockIdx.x * (ETW*TILES_PER_CTA);   // CTA's first e

  if (tid < 64){ hix[tid] = head[b0+tid]; tix[tid] = tail[b0+tid]; vs[tid] = g_v[b0+tid]; }
  for (int i = tid; i < BT*R_; i += 256) us[i] = g_u[b0*R_ + i];
  __syncthreads();   // hix/tix visible to ALL threads before A-tile gather (race fix)

  // ---- A tile (h/t interleaved in 8-row blocks) ----
  const uint4* T = (const uint4*)g_Ebf;
  #pragma unroll
  for (int it = 0; it < 8; it++){
    int idx = it*256 + tid;
    int ch = idx & 15, row = idx >> 4;   // row 0..127
    int bl = ((row >> 4) << 3) | (row & 7);
    int ent = (row & 8) ? tix[bl] : hix[bl];
    uint4 v = T[(size_t)ent*16 + ch];
    *(uint4*)(smc + row*256 + (((uint32_t)ch ^ (row & 7)) << 4)) = v;
  }

  // ---- prefetch B tile 0 (64 rows) via cp.async ----
  #pragma unroll
  for (int it = 0; it < 4; it++){
    int idx = it*256 + tid;
    int ch = idx & 15, row = idx >> 4;   // 0..63
    uint32_t dst = sb + OFF_B0 + row*256 + (((uint32_t)ch ^ (row & 7)) << 4);
    CP_ASYNC16(dst, (const uint4*)g_Ebf + (size_t)(e00 + row)*16 + ch);
  }
  CP_COMMIT();

  // per-thread fragment coordinates: warp (wm 0..1, wn 0..3) owns 64 rows x 16 cols
  int wm = wid >> 2, wn = wid & 3;
  int lrow = lane & 15, lhi = lane >> 4;
  uint32_t a_base[4], a_sw[4];
  #pragma unroll
  for (int mi = 0; mi < 4; mi++){
    int r = wm*64 + mi*16 + lrow;
    a_base[mi] = sb + r*256; a_sw[mi] = (uint32_t)(r & 7);
  }
  uint32_t b_row = (uint32_t)(wn*16 + lrow);          // B row (e) this lane loads
  uint32_t b_sw = b_row & 7;
  int brow = lane >> 2, ecol = (lane & 3)*2;
  int eb = wn*16 + ecol;

  float bacc[4];
  #pragma unroll
  for (int mi = 0; mi < 4; mi++) bacc[mi] = 0.f;

  for (int t = 0; t < TILES_PER_CTA; t++){
    CP_WAIT0();
    __syncthreads();

    if (t < TILES_PER_CTA-1){
      int e0n = e00 + (t+1)*ETW;
      uint32_t boff = ((t+1) & 1) ? OFF_B1 : OFF_B0;
      #pragma unroll
      for (int it = 0; it < 4; it++){
        int idx = it*256 + tid;
        int ch = idx & 15, row = idx >> 4;
        uint32_t dst = sb + boff + row*256 + (((uint32_t)ch ^ (row & 7)) << 4);
        CP_ASYNC16(dst, (const uint4*)g_Ebf + (size_t)(e0n + row)*16 + ch);
      }
      CP_COMMIT();
    }

    uint32_t bbuf = sb + ((t & 1) ? OFF_B1 : OFF_B0);
    uint32_t b_base = bbuf + b_row*256;

    float acc[4][2][4];
    #pragma unroll
    for (int mi = 0; mi < 4; mi++)
      #pragma unroll
      for (int ni = 0; ni < 2; ni++)
        #pragma unroll
        for (int q = 0; q < 4; q++) acc[mi][ni][q] = 0.f;

    #pragma unroll
    for (int kk = 0; kk < 8; kk++){
      uint32_t c = (uint32_t)(kk*2 + lhi);
      uint32_t ra[4][4], rb[4];
      #pragma unroll
      for (int mi = 0; mi < 4; mi++)
        ldm4(ra[mi][0], ra[mi][1], ra[mi][2], ra[mi][3],
             a_base[mi] + ((c ^ a_sw[mi]) << 4));
      ldm4(rb[0], rb[1], rb[2], rb[3], b_base + ((c ^ b_sw) << 4));
      #pragma unroll
      for (int mi = 0; mi < 4; mi++)
        #pragma unroll
        for (int ni = 0; ni < 2; ni++)
          mma16816(acc[mi][ni], ra[mi], rb[ni], rb[2+ni]);
    }

    // ---- in-register epilogue; c/g from L2-hot gmem; sq provably > 0 (no clamp) ----
    int e0t = e00 + t*ETW;
    const float* cg = g_c + e0t + eb;
    const float* gg_p = g_g + e0t + eb;

    #pragma unroll
    for (int ni = 0; ni < 2; ni++){
      float2 gg = __ldg((const float2*)(gg_p + ni*8));
      #pragma unroll
      for (int mi = 0; mi < 4; mi++){
        int bl = (wm*4 + mi)*8 + brow;
        float vb = vs[bl];
        acc[mi][ni][2] = sqrt_approx(fmaf(-2.f, acc[mi][ni][2], vb + gg.x));
        acc[mi][ni][3] = sqrt_approx(fmaf(-2.f, acc[mi][ni][3], vb + gg.y));
      }
    }

    float S1[4][2][2];
    #pragma unroll
    for (int mi = 0; mi < 4; mi++)
      #pragma unroll
      for (int ni = 0; ni < 2; ni++){ S1[mi][ni][0] = 0.f; S1[mi][ni][1] = 0.f; }

    #pragma unroll
    for (int r = 0; r < R_; r++){
      float2 cr[2];
      #pragma unroll
      for (int ni = 0; ni < 2; ni++)
        cr[ni] = __ldg((const float2*)(cg + (size_t)r*E_ + ni*8));
      #pragma unroll
      for (int mi = 0; mi < 4; mi++){
        int bl = (wm*4 + mi)*8 + brow;
        float ur = us[bl*R_ + r];
        #pragma unroll
        for (int ni = 0; ni < 2; ni++){
          S1[mi][ni][0] += sqrt_approx(fmaf(-2.f, acc[mi][ni][0], ur + cr[ni].x));
          S1[mi][ni][1] += sqrt_approx(fmaf(-2.f, acc[mi][ni][1], ur + cr[ni].y));
        }
      }
    }

    #pragma unroll
    for (int mi = 0; mi < 4; mi++){
      float s = 0.f;
      #pragma unroll
      for (int ni = 0; ni < 2; ni++)
        s = fmaf(S1[mi][ni][0], acc[mi][ni][2], fmaf(S1[mi][ni][1], acc[mi][ni][3], s));
      s += __shfl_xor_sync(0xffffffffu, s, 1);
      s += __shfl_xor_sync(0xffffffffu, s, 2);
      bacc[mi] += s;
    }
  }

  // ---- single cross-warp reduction at the end ----
  #pragma unroll
  for (int mi = 0; mi < 4; mi++){
    if ((lane & 3) == 0){
      int bl = (wm*4 + mi)*8 + brow;
      red[wn*64 + bl] = bacc[mi];
    }
  }
  __syncthreads();
  if (tid < 64){
    float s = (red[tid] + red[64+tid]) + (red[128+tid] + red[192+tid]);
    g_part[(size_t)(b0 + tid)*NEG + blockIdx.x] = s;
  }
}

// ---------------- final deterministic reduction (64 partials per b) ----------------
__global__ void k_final(float* __restrict__ out){
  int wid = threadIdx.x >> 5, lane = threadIdx.x & 31;
  int b = blockIdx.x*8 + wid;
  const float* p = g_part + (size_t)b*NEG;
  float s = p[lane] + p[lane+32];
  s = wsum(s);
  if (lane == 0) out[b] = s * (1.f/(float)E_);
}

extern "C" void kernel_launch(void* const* d_in, const int* in_sizes, int n_in,
                              void* d_out, int out_size){
  const int*   head  = (const int*)d_in[0];
  const int*   tail  = (const int*)d_in[1];
  const int*   qrel  = (const int*)d_in[2];
  // d_in[3] = depth (fixed at 1, unused)
  const float* Etab  = (const float*)d_in[4];
  const float* rules = (const float*)d_in[5];
  float* out = (float*)d_out;

  cudaFuncSetAttribute(k_main, cudaFuncAttributeMaxDynamicSharedMemorySize, SMEM_BYTES);
  cudaFuncSetAttribute(k_rz, cudaFuncAttributeMaxDynamicSharedMemorySize, RZ_SMEM);

  k_pre<<<NCONV + NBATCH + 1, 256>>>(Etab, rules, head, tail, qrel);
  k_rz<<<E_/256, 256, RZ_SMEM>>>();
  dim3 grid(NEG, B_/BT);
  k_main<<<grid, 256, SMEM_BYTES>>>(head, tail);
  k_final<<<B_/8, 256>>>(out);
}